// round 3
// baseline (speedup 1.0000x reference)
#include <cuda_runtime.h>
#include <math.h>

#define NTOK  32768      // n = d*h*w
#define CIN   128        // channels
#define HID   256        // heads * dim_head
#define OQKV  768        // 3 * HID
#define NB    4          // batch
#define NHEAD 8
#define DHEAD 32
#define SCALE 0.1767766952966369f  // 32^-0.5

// ---------------- scratch (device globals: allocation-free rule) ----------------
__device__ float g_qkv[NB * OQKV * NTOK];        // 384 MB: q|k|v rows, [b][o][n]
__device__ float g_kmax[NB * HID];               // per (b,h,d) row max of k
__device__ float g_ksum[NB * HID];               // per (b,h,d) row sum of exp
__device__ float g_ctx[NB * NHEAD * DHEAD * DHEAD]; // raw Σ exp(k-max)·v
__device__ float g_M[NB * CIN * HID];            // folded projection matrix

// =====================================================================
// SGEMM: C[O x N] = A[O x K] * B[K x N]  (+bias), all row-major.
// 128x128 block tile, BK=16, 256 threads, 8x8 per-thread tile,
// double-buffered shared memory, one barrier per K-chunk.
// =====================================================================
__global__ __launch_bounds__(256, 2)
void sgemm_kernel(const float* __restrict__ A, const float* __restrict__ B,
                  float* __restrict__ C, const float* __restrict__ bias,
                  int K, int N,
                  long long sA, long long sB, long long sC, int useBias)
{
    __shared__ __align__(16) float As[2][16][132];  // [buf][k][m], pad 132 (528B, 16B-mult)
    __shared__ __align__(16) float Bs[2][16][128];  // [buf][k][n]

    const int tid = threadIdx.x;
    const float* Ab = A + (long long)blockIdx.z * sA + (long long)blockIdx.y * 128 * K;
    const float* Bb = B + (long long)blockIdx.z * sB + (long long)blockIdx.x * 128;
    float* Cb = C + (long long)blockIdx.z * sC + (long long)blockIdx.y * 128 * N
                  + (long long)blockIdx.x * 128;

    const int aRow = tid >> 2;          // 0..63 (plus +64 row)
    const int aK   = (tid & 3) << 2;    // 0,4,8,12
    const int bK   = tid >> 5;          // 0..7 (plus +8 row)
    const int bCol = (tid & 31) << 2;   // 0..124

    float4 ra0, ra1, rb0, rb1;

    // prologue: chunk 0 -> buffer 0
    ra0 = *(const float4*)(Ab + (long long)aRow * K + aK);
    ra1 = *(const float4*)(Ab + (long long)(aRow + 64) * K + aK);
    rb0 = *(const float4*)(Bb + (long long)bK * N + bCol);
    rb1 = *(const float4*)(Bb + (long long)(bK + 8) * N + bCol);

    As[0][aK + 0][aRow] = ra0.x; As[0][aK + 1][aRow] = ra0.y;
    As[0][aK + 2][aRow] = ra0.z; As[0][aK + 3][aRow] = ra0.w;
    As[0][aK + 0][aRow + 64] = ra1.x; As[0][aK + 1][aRow + 64] = ra1.y;
    As[0][aK + 2][aRow + 64] = ra1.z; As[0][aK + 3][aRow + 64] = ra1.w;
    *(float4*)&Bs[0][bK][bCol]     = rb0;
    *(float4*)&Bs[0][bK + 8][bCol] = rb1;
    __syncthreads();

    float acc[8][8];
    #pragma unroll
    for (int i = 0; i < 8; ++i)
        #pragma unroll
        for (int j = 0; j < 8; ++j)
            acc[i][j] = 0.f;

    const int row0 = (tid >> 4) << 3;
    const int col0 = (tid & 15) << 3;

    const int nChunks = K >> 4;
    for (int c = 0; c < nChunks; ++c) {
        const int cur = c & 1;
        const int nxt = cur ^ 1;
        const bool more = (c + 1 < nChunks);
        if (more) {
            const float* Ac = Ab + (c + 1) * 16;
            ra0 = *(const float4*)(Ac + (long long)aRow * K + aK);
            ra1 = *(const float4*)(Ac + (long long)(aRow + 64) * K + aK);
            const float* Bc = Bb + (long long)(c + 1) * 16 * N;
            rb0 = *(const float4*)(Bc + (long long)bK * N + bCol);
            rb1 = *(const float4*)(Bc + (long long)(bK + 8) * N + bCol);
        }
        #pragma unroll
        for (int kk = 0; kk < 16; ++kk) {
            float a[8], b[8];
            *(float4*)&a[0] = *(const float4*)&As[cur][kk][row0];
            *(float4*)&a[4] = *(const float4*)&As[cur][kk][row0 + 4];
            *(float4*)&b[0] = *(const float4*)&Bs[cur][kk][col0];
            *(float4*)&b[4] = *(const float4*)&Bs[cur][kk][col0 + 4];
            #pragma unroll
            for (int i = 0; i < 8; ++i)
                #pragma unroll
                for (int j = 0; j < 8; ++j)
                    acc[i][j] = fmaf(a[i], b[j], acc[i][j]);
        }
        if (more) {
            As[nxt][aK + 0][aRow] = ra0.x; As[nxt][aK + 1][aRow] = ra0.y;
            As[nxt][aK + 2][aRow] = ra0.z; As[nxt][aK + 3][aRow] = ra0.w;
            As[nxt][aK + 0][aRow + 64] = ra1.x; As[nxt][aK + 1][aRow + 64] = ra1.y;
            As[nxt][aK + 2][aRow + 64] = ra1.z; As[nxt][aK + 3][aRow + 64] = ra1.w;
            *(float4*)&Bs[nxt][bK][bCol]     = rb0;
            *(float4*)&Bs[nxt][bK + 8][bCol] = rb1;
        }
        __syncthreads();
    }

    #pragma unroll
    for (int i = 0; i < 8; ++i) {
        const int r = row0 + i;
        const float bv = useBias ? bias[blockIdx.y * 128 + r] : 0.f;
        float4 o0 = make_float4(acc[i][0] + bv, acc[i][1] + bv, acc[i][2] + bv, acc[i][3] + bv);
        float4 o1 = make_float4(acc[i][4] + bv, acc[i][5] + bv, acc[i][6] + bv, acc[i][7] + bv);
        *(float4*)(Cb + (long long)r * N + col0)     = o0;
        *(float4*)(Cb + (long long)r * N + col0 + 4) = o1;
    }
}

// =====================================================================
// q softmax over the 32 feature dims of each head, * SCALE, in place.
// One thread per (b, h, n); 32 values held in registers.
// =====================================================================
__global__ void qsoftmax_kernel()
{
    const int idx = blockIdx.x * blockDim.x + threadIdx.x;  // 4*8*32768 total
    const int n  = idx & (NTOK - 1);
    const int hb = idx >> 15;
    const int h  = hb & (NHEAD - 1);
    const int b  = hb >> 3;

    float* qp = g_qkv + ((long long)b * OQKV + (long long)h * DHEAD) * NTOK + n;

    float v[32];
    float m = -1e30f;
    #pragma unroll
    for (int d = 0; d < 32; ++d) {
        v[d] = qp[(long long)d * NTOK];
        m = fmaxf(m, v[d]);
    }
    float s = 0.f;
    #pragma unroll
    for (int d = 0; d < 32; ++d) {
        v[d] = __expf(v[d] - m);
        s += v[d];
    }
    const float inv = SCALE / s;
    #pragma unroll
    for (int d = 0; d < 32; ++d)
        qp[(long long)d * NTOK] = v[d] * inv;
}

// =====================================================================
// k row stats: online (max, sumexp) over n=32768 per (b,h,d) row.
// One block (256 threads) per row; also zeroes g_ctx for this launch.
// =====================================================================
__global__ void kstats_kernel()
{
    const int row = blockIdx.x;          // b*256 + (h*32+d), 1024 rows
    const int t = threadIdx.x;
    const int b = row >> 8;
    const int hd = row & 255;
    const float* kr = g_qkv + ((long long)b * OQKV + HID + hd) * NTOK;

    float m = -1e30f, s = 0.f;
    for (int n = t; n < NTOK; n += 256) {
        const float x = kr[n];
        const float nm = fmaxf(m, x);
        s = s * __expf(m - nm) + __expf(x - nm);
        m = nm;
    }

    __shared__ float sm[256], ss[256];
    sm[t] = m; ss[t] = s;
    __syncthreads();
    for (int o = 128; o > 0; o >>= 1) {
        if (t < o) {
            const float m2 = sm[t + o], s2 = ss[t + o];
            const float nm = fmaxf(sm[t], m2);
            ss[t] = ss[t] * __expf(sm[t] - nm) + s2 * __expf(m2 - nm);
            sm[t] = nm;
        }
        __syncthreads();
    }
    if (t == 0) { g_kmax[row] = sm[0]; g_ksum[row] = ss[0]; }
    if (t < 32) g_ctx[row * 32 + t] = 0.f;   // 1024*32 = full ctx buffer
}

// =====================================================================
// context: ctx[b,h,d,e] += Σ_n exp(k[d,n]-max_d) * v[e,n]
// Grid (16 n-chunks, 8 heads, 4 batch). 256 threads = 16 n-slots x
// (16 threads covering 32x32 with 8x8 register tiles). Slot partials
// reduced via shared atomics, then global atomics (zeroed in kstats).
// =====================================================================
__global__ __launch_bounds__(256, 2)
void context_kernel()
{
    const int b = blockIdx.z, h = blockIdx.y, cx = blockIdx.x;
    const int t = threadIdx.x;
    const float* kbase = g_qkv + ((long long)b * OQKV + HID     + h * DHEAD) * NTOK;
    const float* vbase = g_qkv + ((long long)b * OQKV + 2 * HID + h * DHEAD) * NTOK;

    __shared__ float ks[32][17];
    __shared__ float vs[32][17];
    __shared__ float red[32][33];
    __shared__ float kmx[32];

    if (t < 32) kmx[t] = g_kmax[(b * NHEAD + h) * DHEAD + t];
    for (int i = t; i < 1024; i += 256) red[i >> 5][i & 31] = 0.f;
    __syncthreads();

    const int slot = t >> 4;          // n slot 0..15
    const int l    = t & 15;
    const int ti   = l >> 2;          // d-tile 0..3 (rows ti*8..+7)
    const int tj   = l & 3;           // e-tile 0..3 (cols tj*8..+7)

    const int ld = t >> 3;            // loader: d row 0..31
    const int ln = (t & 7) << 1;      // loader: n pair 0..14
    const float kmr = kmx[ld];

    float acc[8][8];
    #pragma unroll
    for (int i = 0; i < 8; ++i)
        #pragma unroll
        for (int j = 0; j < 8; ++j)
            acc[i][j] = 0.f;

    const int nbase0 = cx * (NTOK / 16);          // 2048-wide chunk
    for (int slab = 0; slab < (NTOK / 16) / 16; ++slab) {   // 128 slabs of 16 n
        const int nb = nbase0 + slab * 16;
        const float2 kv = *(const float2*)(kbase + (long long)ld * NTOK + nb + ln);
        const float2 vv = *(const float2*)(vbase + (long long)ld * NTOK + nb + ln);
        ks[ld][ln]     = __expf(kv.x - kmr);
        ks[ld][ln + 1] = __expf(kv.y - kmr);
        vs[ld][ln]     = vv.x;
        vs[ld][ln + 1] = vv.y;
        __syncthreads();

        float ka[8], va[8];
        #pragma unroll
        for (int i = 0; i < 8; ++i) ka[i] = ks[ti * 8 + i][slot];
        #pragma unroll
        for (int j = 0; j < 8; ++j) va[j] = vs[tj * 8 + j][slot];
        #pragma unroll
        for (int i = 0; i < 8; ++i)
            #pragma unroll
            for (int j = 0; j < 8; ++j)
                acc[i][j] = fmaf(ka[i], va[j], acc[i][j]);
        __syncthreads();
    }

    #pragma unroll
    for (int i = 0; i < 8; ++i)
        #pragma unroll
        for (int j = 0; j < 8; ++j)
            atomicAdd(&red[ti * 8 + i][tj * 8 + j], acc[i][j]);
    __syncthreads();

    float* ctx = g_ctx + (b * NHEAD + h) * (DHEAD * DHEAD);
    for (int i = t; i < 1024; i += 256)
        atomicAdd(&ctx[i], red[i >> 5][i & 31]);
}

// =====================================================================
// Fold W_out, context, and k-softmax normalization into M:
// M[b][co][h*32+d] = (Σ_e W_out[co][h*32+e] * ctx[b,h,d,e]) / ksum[b,h,d]
// =====================================================================
__global__ void mcombine_kernel(const float* __restrict__ w_out)
{
    const int idx = blockIdx.x * 256 + threadIdx.x;   // 4*128*256
    const int col = idx & 255;          // h*32+d
    const int co  = (idx >> 8) & 127;
    const int b   = idx >> 15;
    const int h = col >> 5, d = col & 31;

    const float* wrow = w_out + co * HID + h * DHEAD;
    const float* cr = g_ctx + ((b * NHEAD + h) * DHEAD + d) * DHEAD;
    float s = 0.f;
    #pragma unroll
    for (int e = 0; e < 32; ++e) s = fmaf(wrow[e], cr[e], s);
    g_M[((long long)b * CIN + co) * HID + col] = s / g_ksum[b * HID + col];
}

// =====================================================================
extern "C" void kernel_launch(void* const* d_in, const int* in_sizes, int n_in,
                              void* d_out, int out_size)
{
    const float* x     = (const float*)d_in[0];   // [4,128,32768]
    const float* w_qkv = (const float*)d_in[1];   // [768,128]
    const float* w_out = (const float*)d_in[2];   // [128,256]
    const float* b_out = (const float*)d_in[3];   // [128]
    float* out = (float*)d_out;                   // [4,128,32768]

    float *qkv_p = nullptr, *M_p = nullptr;
    cudaGetSymbolAddress((void**)&qkv_p, g_qkv);
    cudaGetSymbolAddress((void**)&M_p, g_M);

    // 1) qkv = W_qkv @ x   (per batch)
    dim3 g1(NTOK / 128, OQKV / 128, NB);
    sgemm_kernel<<<g1, 256>>>(w_qkv, x, qkv_p, nullptr, CIN, NTOK,
                              0LL, (long long)CIN * NTOK, (long long)OQKV * NTOK, 0);

    // 2) q softmax (in place, * SCALE)
    qsoftmax_kernel<<<(NB * NHEAD * NTOK) / 256, 256>>>();

    // 3) k row stats (+ zero ctx)
    kstats_kernel<<<NB * HID, 256>>>();

    // 4) context accumulation
    dim3 g4(16, NHEAD, NB);
    context_kernel<<<g4, 256>>>();

    // 5) fold projection matrix
    mcombine_kernel<<<(NB * CIN * HID) / 256, 256>>>(w_out);

    // 6) out = M @ q_soft + b_out  (writes d_out directly)
    dim3 g6(NTOK / 128, 1, NB);
    sgemm_kernel<<<g6, 256>>>(M_p, qkv_p, out, b_out, HID, NTOK,
                              (long long)CIN * HID, (long long)OQKV * NTOK,
                              (long long)CIN * NTOK, 1);
}

// round 4
// speedup vs baseline: 1.1302x; 1.1302x over previous
#include <cuda_runtime.h>
#include <math.h>

#define NTOK  32768      // n = d*h*w
#define CIN   128        // channels
#define HID   256        // heads * dim_head
#define OQKV  768        // 3 * HID
#define NB    4          // batch
#define NHEAD 8
#define DHEAD 32
#define SCALE 0.1767766952966369f  // 32^-0.5

// ---------------- scratch (device globals: allocation-free rule) ----------------
__device__ float g_qkv[NB * OQKV * NTOK];            // q|k|v rows, [b][o][n]
__device__ float g_ksum[NB * HID];                   // per (b,h,d): sum exp(k)
__device__ float g_ctx[NB * NHEAD * DHEAD * DHEAD];  // raw sum exp(k)*v
__device__ float g_M[NB * CIN * HID];                // folded projection matrix

// =====================================================================
// SGEMM: C[O x N] = A[O x K] * B[K x N]  (+bias), all row-major.
// 128x128 block tile, BK=16, 256 threads, 8x8 per-thread tile held as
// f32x2 packed accumulators (FFMA2: 2 FMAs per issue slot).
// Double-buffered shared memory, one barrier per K-chunk.
// =====================================================================
__global__ __launch_bounds__(256, 2)
void sgemm_kernel(const float* __restrict__ A, const float* __restrict__ B,
                  float* __restrict__ C, const float* __restrict__ bias,
                  int K, int N,
                  long long sA, long long sB, long long sC, int useBias)
{
    __shared__ __align__(16) float As[2][16][132];  // [buf][k][m]
    __shared__ __align__(16) float Bs[2][16][128];  // [buf][k][n]

    const int tid = threadIdx.x;
    const float* Ab = A + (long long)blockIdx.z * sA + (long long)blockIdx.y * 128 * K;
    const float* Bb = B + (long long)blockIdx.z * sB + (long long)blockIdx.x * 128;
    float* Cb = C + (long long)blockIdx.z * sC + (long long)blockIdx.y * 128 * N
                  + (long long)blockIdx.x * 128;

    const int aRow = tid >> 2;          // 0..63 (plus +64 row)
    const int aK   = (tid & 3) << 2;    // 0,4,8,12
    const int bK   = tid >> 5;          // 0..7 (plus +8 row)
    const int bCol = (tid & 31) << 2;   // 0..124

    float4 ra0, ra1, rb0, rb1;

    // prologue: chunk 0 -> buffer 0
    ra0 = *(const float4*)(Ab + (long long)aRow * K + aK);
    ra1 = *(const float4*)(Ab + (long long)(aRow + 64) * K + aK);
    rb0 = *(const float4*)(Bb + (long long)bK * N + bCol);
    rb1 = *(const float4*)(Bb + (long long)(bK + 8) * N + bCol);

    As[0][aK + 0][aRow] = ra0.x; As[0][aK + 1][aRow] = ra0.y;
    As[0][aK + 2][aRow] = ra0.z; As[0][aK + 3][aRow] = ra0.w;
    As[0][aK + 0][aRow + 64] = ra1.x; As[0][aK + 1][aRow + 64] = ra1.y;
    As[0][aK + 2][aRow + 64] = ra1.z; As[0][aK + 3][aRow + 64] = ra1.w;
    *(float4*)&Bs[0][bK][bCol]     = rb0;
    *(float4*)&Bs[0][bK + 8][bCol] = rb1;
    __syncthreads();

    unsigned long long accp[8][4];   // 8 rows x 4 packed column-pairs
    #pragma unroll
    for (int i = 0; i < 8; ++i)
        #pragma unroll
        for (int j = 0; j < 4; ++j)
            accp[i][j] = 0ULL;       // bit pattern of (0.f, 0.f)

    const int row0 = (tid >> 4) << 3;
    const int col0 = (tid & 15) << 3;

    const int nChunks = K >> 4;
    for (int c = 0; c < nChunks; ++c) {
        const int cur = c & 1;
        const int nxt = cur ^ 1;
        const bool more = (c + 1 < nChunks);
        if (more) {
            const float* Ac = Ab + (c + 1) * 16;
            ra0 = *(const float4*)(Ac + (long long)aRow * K + aK);
            ra1 = *(const float4*)(Ac + (long long)(aRow + 64) * K + aK);
            const float* Bc = Bb + (long long)(c + 1) * 16 * N;
            rb0 = *(const float4*)(Bc + (long long)bK * N + bCol);
            rb1 = *(const float4*)(Bc + (long long)(bK + 8) * N + bCol);
        }
        #pragma unroll
        for (int kk = 0; kk < 16; ++kk) {
            float a[8];
            *(float4*)&a[0] = *(const float4*)&As[cur][kk][row0];
            *(float4*)&a[4] = *(const float4*)&As[cur][kk][row0 + 4];
            unsigned long long b2[4];
            {
                ulonglong2 t0 = *(const ulonglong2*)&Bs[cur][kk][col0];
                ulonglong2 t1 = *(const ulonglong2*)&Bs[cur][kk][col0 + 4];
                b2[0] = t0.x; b2[1] = t0.y; b2[2] = t1.x; b2[3] = t1.y;
            }
            #pragma unroll
            for (int i = 0; i < 8; ++i) {
                unsigned long long a2;
                asm("mov.b64 %0, {%1, %1};" : "=l"(a2) : "f"(a[i]));
                #pragma unroll
                for (int j = 0; j < 4; ++j)
                    asm("fma.rn.f32x2 %0, %1, %2, %0;"
                        : "+l"(accp[i][j]) : "l"(a2), "l"(b2[j]));
            }
        }
        if (more) {
            As[nxt][aK + 0][aRow] = ra0.x; As[nxt][aK + 1][aRow] = ra0.y;
            As[nxt][aK + 2][aRow] = ra0.z; As[nxt][aK + 3][aRow] = ra0.w;
            As[nxt][aK + 0][aRow + 64] = ra1.x; As[nxt][aK + 1][aRow + 64] = ra1.y;
            As[nxt][aK + 2][aRow + 64] = ra1.z; As[nxt][aK + 3][aRow + 64] = ra1.w;
            *(float4*)&Bs[nxt][bK][bCol]     = rb0;
            *(float4*)&Bs[nxt][bK + 8][bCol] = rb1;
        }
        __syncthreads();
    }

    #pragma unroll
    for (int i = 0; i < 8; ++i) {
        float o[8];
        #pragma unroll
        for (int j = 0; j < 4; ++j)
            asm("mov.b64 {%0, %1}, %2;"
                : "=f"(o[2 * j]), "=f"(o[2 * j + 1]) : "l"(accp[i][j]));
        const int r = row0 + i;
        const float bv = useBias ? bias[blockIdx.y * 128 + r] : 0.f;
        float4 o0 = make_float4(o[0] + bv, o[1] + bv, o[2] + bv, o[3] + bv);
        float4 o1 = make_float4(o[4] + bv, o[5] + bv, o[6] + bv, o[7] + bv);
        *(float4*)(Cb + (long long)r * N + col0)     = o0;
        *(float4*)(Cb + (long long)r * N + col0 + 4) = o1;
    }
}

// =====================================================================
// q softmax over the 32 feature dims of each head, * SCALE, in place.
// =====================================================================
__global__ void qsoftmax_kernel()
{
    const int idx = blockIdx.x * blockDim.x + threadIdx.x;  // 4*8*32768 total
    const int n  = idx & (NTOK - 1);
    const int hb = idx >> 15;
    const int h  = hb & (NHEAD - 1);
    const int b  = hb >> 3;

    float* qp = g_qkv + ((long long)b * OQKV + (long long)h * DHEAD) * NTOK + n;

    float v[32];
    float m = -1e30f;
    #pragma unroll
    for (int d = 0; d < 32; ++d) {
        v[d] = qp[(long long)d * NTOK];
        m = fmaxf(m, v[d]);
    }
    float s = 0.f;
    #pragma unroll
    for (int d = 0; d < 32; ++d) {
        v[d] = __expf(v[d] - m);
        s += v[d];
    }
    const float inv = SCALE / s;
    #pragma unroll
    for (int d = 0; d < 32; ++d)
        qp[(long long)d * NTOK] = v[d] * inv;
}

// =====================================================================
// context: ctx[b,h,d,e] += sum_n exp(k[d,n]) * v[e,n]
//          ksum[b,h,d]  += sum_n exp(k[d,n])
// No max subtraction: k ~ N(0,1), |k| < ~6, exp is fp32-safe, and the
// exp(-max) factor cancels between ctx and ksum in mcombine anyway.
// Grid (16 n-chunks, 8 heads, 4 batch). 32-n slabs, register-prefetch
// double buffering so global latency overlaps the FMA phase.
// g_ctx / g_ksum must be zeroed before launch (memset nodes).
// =====================================================================
__global__ __launch_bounds__(256, 2)
void context_kernel()
{
    const int b = blockIdx.z, h = blockIdx.y, cx = blockIdx.x;
    const int t = threadIdx.x;
    const float* kbase = g_qkv + ((long long)b * OQKV + HID     + h * DHEAD) * NTOK;
    const float* vbase = g_qkv + ((long long)b * OQKV + 2 * HID + h * DHEAD) * NTOK;

    __shared__ float ks[32][33];   // odd stride: conflict-free column reads
    __shared__ float vs[32][33];
    __shared__ float red[32][33];

    for (int i = t; i < 1024; i += 256) red[i >> 5][i & 31] = 0.f;

    const int ld = t >> 3;            // loader: d row 0..31
    const int ln = (t & 7) << 2;      // loader: 4 n per thread
    const int slot = t >> 4;          // n slot 0..15 (2 n per slab each)
    const int l    = t & 15;
    const int ti   = l >> 2;          // d-tile 0..3
    const int tj   = l & 3;           // e-tile 0..3

    float acc[8][8];
    #pragma unroll
    for (int i = 0; i < 8; ++i)
        #pragma unroll
        for (int j = 0; j < 8; ++j)
            acc[i][j] = 0.f;
    float ksum_part = 0.f;

    const int nbase0 = cx * (NTOK / 16);             // 2048-wide chunk
    const int NS = (NTOK / 16) / 32;                 // 64 slabs of 32 n

    const float* krow = kbase + (long long)ld * NTOK + nbase0 + ln;
    const float* vrow = vbase + (long long)ld * NTOK + nbase0 + ln;
    float4 kr = *(const float4*)krow;
    float4 vr = *(const float4*)vrow;

    for (int slab = 0; slab < NS; ++slab) {
        const float e0 = __expf(kr.x), e1 = __expf(kr.y);
        const float e2 = __expf(kr.z), e3 = __expf(kr.w);
        ksum_part += (e0 + e1) + (e2 + e3);
        ks[ld][ln] = e0; ks[ld][ln + 1] = e1; ks[ld][ln + 2] = e2; ks[ld][ln + 3] = e3;
        vs[ld][ln] = vr.x; vs[ld][ln + 1] = vr.y; vs[ld][ln + 2] = vr.z; vs[ld][ln + 3] = vr.w;
        __syncthreads();

        if (slab + 1 < NS) {                         // prefetch next slab
            kr = *(const float4*)(krow + (slab + 1) * 32);
            vr = *(const float4*)(vrow + (slab + 1) * 32);
        }

        #pragma unroll
        for (int q = 0; q < 2; ++q) {
            const int n = slot * 2 + q;
            float ka[8], va[8];
            #pragma unroll
            for (int i = 0; i < 8; ++i) ka[i] = ks[ti * 8 + i][n];
            #pragma unroll
            for (int j = 0; j < 8; ++j) va[j] = vs[tj * 8 + j][n];
            #pragma unroll
            for (int i = 0; i < 8; ++i)
                #pragma unroll
                for (int j = 0; j < 8; ++j)
                    acc[i][j] = fmaf(ka[i], va[j], acc[i][j]);
        }
        __syncthreads();
    }

    // ksum: reduce over the 8 loader threads sharing row ld (consecutive lanes)
    #pragma unroll
    for (int o = 4; o > 0; o >>= 1)
        ksum_part += __shfl_down_sync(0xffffffffu, ksum_part, o, 8);
    if ((t & 7) == 0)
        atomicAdd(&g_ksum[(b * NHEAD + h) * DHEAD + ld], ksum_part);

    #pragma unroll
    for (int i = 0; i < 8; ++i)
        #pragma unroll
        for (int j = 0; j < 8; ++j)
            atomicAdd(&red[ti * 8 + i][tj * 8 + j], acc[i][j]);
    __syncthreads();

    float* ctx = g_ctx + (b * NHEAD + h) * (DHEAD * DHEAD);
    for (int i = t; i < 1024; i += 256)
        atomicAdd(&ctx[i], red[i >> 5][i & 31]);
}

// =====================================================================
// Fold W_out, context, and k-softmax normalization into M:
// M[b][co][h*32+d] = (sum_e W_out[co][h*32+e] * ctx[b,h,d,e]) / ksum[b,h,d]
// =====================================================================
__global__ void mcombine_kernel(const float* __restrict__ w_out)
{
    const int idx = blockIdx.x * 256 + threadIdx.x;   // 4*128*256
    const int col = idx & 255;          // h*32+d
    const int co  = (idx >> 8) & 127;
    const int b   = idx >> 15;
    const int h = col >> 5, d = col & 31;

    const float* wrow = w_out + co * HID + h * DHEAD;
    const float* cr = g_ctx + ((b * NHEAD + h) * DHEAD + d) * DHEAD;
    float s = 0.f;
    #pragma unroll
    for (int e = 0; e < 32; ++e) s = fmaf(wrow[e], cr[e], s);
    g_M[((long long)b * CIN + co) * HID + col] = s / g_ksum[b * HID + col];
}

// =====================================================================
extern "C" void kernel_launch(void* const* d_in, const int* in_sizes, int n_in,
                              void* d_out, int out_size)
{
    const float* x     = (const float*)d_in[0];   // [4,128,32768]
    const float* w_qkv = (const float*)d_in[1];   // [768,128]
    const float* w_out = (const float*)d_in[2];   // [128,256]
    const float* b_out = (const float*)d_in[3];   // [128]
    float* out = (float*)d_out;                   // [4,128,32768]

    float *qkv_p = nullptr, *M_p = nullptr, *ctx_p = nullptr, *ksum_p = nullptr;
    cudaGetSymbolAddress((void**)&qkv_p, g_qkv);
    cudaGetSymbolAddress((void**)&M_p, g_M);
    cudaGetSymbolAddress((void**)&ctx_p, g_ctx);
    cudaGetSymbolAddress((void**)&ksum_p, g_ksum);

    // 1) qkv = W_qkv @ x   (per batch)
    dim3 g1(NTOK / 128, OQKV / 128, NB);
    sgemm_kernel<<<g1, 256>>>(w_qkv, x, qkv_p, nullptr, CIN, NTOK,
                              0LL, (long long)CIN * NTOK, (long long)OQKV * NTOK, 0);

    // 2) q softmax (in place, * SCALE)
    qsoftmax_kernel<<<(NB * NHEAD * NTOK) / 256, 256>>>();

    // 3) zero accumulators (graph-capturable memset nodes)
    cudaMemsetAsync(ctx_p, 0, sizeof(float) * NB * NHEAD * DHEAD * DHEAD);
    cudaMemsetAsync(ksum_p, 0, sizeof(float) * NB * HID);

    // 4) context + ksum accumulation
    dim3 g4(16, NHEAD, NB);
    context_kernel<<<g4, 256>>>();

    // 5) fold projection matrix
    mcombine_kernel<<<(NB * CIN * HID) / 256, 256>>>(w_out);

    // 6) out = M @ q_soft + b_out  (writes d_out directly)
    dim3 g6(NTOK / 128, 1, NB);
    sgemm_kernel<<<g6, 256>>>(M_p, qkv_p, out, b_out, HID, NTOK,
                              (long long)CIN * HID, (long long)OQKV * NTOK,
                              (long long)CIN * NTOK, 1);
}

// round 6
// speedup vs baseline: 1.7904x; 1.5841x over previous
#include <cuda_runtime.h>
#include <cuda_bf16.h>
#include <math.h>
#include <stdint.h>

#define NTOK  32768      // n = d*h*w
#define CIN   128        // channels
#define HID   256        // heads * dim_head
#define OQKV  768        // 3 * HID
#define NB    4          // batch
#define NHEAD 8
#define DHEAD 32
#define SCALE 0.1767766952966369f  // 32^-0.5

// ---------------- scratch (device globals: allocation-free rule) ----------------
__device__ __align__(256) float g_qkv[NB * OQKV * NTOK];           // q|k|v fp32, [b][o][n]
__device__ __align__(256) float g_ksum[NB * HID];                  // per (b,h,d): sum exp(k)
__device__ __align__(256) float g_ctx[NB * NHEAD * DHEAD * DHEAD]; // raw sum exp(k)*v
__device__ __align__(256) __nv_bfloat16 g_xt_hi[NB * NTOK * CIN];  // x^T hi  [b][n][c]
__device__ __align__(256) __nv_bfloat16 g_xt_lo[NB * NTOK * CIN];  // x^T lo
__device__ __align__(256) __nv_bfloat16 g_wq_hi[OQKV * CIN];       // W_qkv hi [o][c]
__device__ __align__(256) __nv_bfloat16 g_wq_lo[OQKV * CIN];
__device__ __align__(256) __nv_bfloat16 g_qt_hi[NB * NTOK * HID];  // q_soft^T hi [b][n][hd]
__device__ __align__(256) __nv_bfloat16 g_qt_lo[NB * NTOK * HID];
__device__ __align__(256) __nv_bfloat16 g_M_hi[NB * CIN * HID];    // folded proj hi [b][co][hd]
__device__ __align__(256) __nv_bfloat16 g_M_lo[NB * CIN * HID];

// ====================== mma.sync helpers (baseline PTX, no 'a' features) ======================
__device__ __forceinline__ uint32_t smem_u32(const void* p) {
    uint32_t a;
    asm("{ .reg .u64 t; cvta.to.shared.u64 t, %1; cvt.u32.u64 %0, t; }" : "=r"(a) : "l"(p));
    return a;
}
__device__ __forceinline__ void ldsm4(uint32_t a, uint32_t* r) {
    asm volatile("ldmatrix.sync.aligned.m8n8.x4.shared.b16 {%0,%1,%2,%3}, [%4];"
                 : "=r"(r[0]), "=r"(r[1]), "=r"(r[2]), "=r"(r[3]) : "r"(a));
}
__device__ __forceinline__ void ldsm2(uint32_t a, uint32_t* r) {
    asm volatile("ldmatrix.sync.aligned.m8n8.x2.shared.b16 {%0,%1}, [%2];"
                 : "=r"(r[0]), "=r"(r[1]) : "r"(a));
}
__device__ __forceinline__ void mma_bf16(float* c, const uint32_t* a, const uint32_t* b) {
    asm volatile("mma.sync.aligned.m16n8k16.row.col.f32.bf16.bf16.f32 "
                 "{%0,%1,%2,%3}, {%4,%5,%6,%7}, {%8,%9}, {%0,%1,%2,%3};"
                 : "+f"(c[0]), "+f"(c[1]), "+f"(c[2]), "+f"(c[3])
                 : "r"(a[0]), "r"(a[1]), "r"(a[2]), "r"(a[3]), "r"(b[0]), "r"(b[1]));
}

// =====================================================================
// HMMA GEMM with bf16 hi/lo split (3 product terms, fp32 accumulate):
//   C[128 x 128] tile = A[128 x K] @ B[128 x K]^T
// A row-major [m][k], B row-major [n][k] (both hi/lo bf16).
// 256 threads = 8 warps (2 m x 4 n), warp tile 64x32, BK=32 chunks with
// register-prefetch. Smem rows padded to 40 elems (80B) -> conflict-free
// ldmatrix. C fp32, leading dim NTOK. Grid (n-tiles, m-tiles, NB).
// =====================================================================
#define LDT 40   // padded row stride in bf16 elements

template<bool BIAS>
__global__ __launch_bounds__(256, 1)
void gemm_mma_kernel(const __nv_bfloat16* __restrict__ Ahi, const __nv_bfloat16* __restrict__ Alo,
                     const __nv_bfloat16* __restrict__ Bhi, const __nv_bfloat16* __restrict__ Blo,
                     float* __restrict__ C, const float* __restrict__ bias, int K,
                     long long sA, long long sB, long long sC)
{
    __shared__ __align__(16) __nv_bfloat16 sm[4][128 * LDT];  // Ah, Al, Bh, Bl

    const int tid = threadIdx.x, wid = tid >> 5, lane = tid & 31;
    const int nt = blockIdx.x, mt = blockIdx.y, b = blockIdx.z;

    const __nv_bfloat16* Ah = Ahi + (long long)b * sA + (long long)mt * 128 * K;
    const __nv_bfloat16* Al = Alo + (long long)b * sA + (long long)mt * 128 * K;
    const __nv_bfloat16* Bh = Bhi + (long long)b * sB + (long long)nt * 128 * K;
    const __nv_bfloat16* Bl = Blo + (long long)b * sB + (long long)nt * 128 * K;
    float* Cb = C + (long long)b * sC + (long long)mt * 128 * NTOK + (long long)nt * 128;

    // loader: 512 16B-chunks per tile; thread handles chunks tid and tid+256
    const int r0c = tid >> 2,        k80 = (tid & 3) << 3;           // chunk tid
    const int r1c = (tid + 256) >> 2, k81 = ((tid + 256) & 3) << 3;  // chunk tid+256

    uint4 p[4][2];
    {
        const long long o0 = (long long)r0c * K + k80;
        const long long o1 = (long long)r1c * K + k81;
        p[0][0] = *(const uint4*)(Ah + o0); p[0][1] = *(const uint4*)(Ah + o1);
        p[1][0] = *(const uint4*)(Al + o0); p[1][1] = *(const uint4*)(Al + o1);
        p[2][0] = *(const uint4*)(Bh + o0); p[2][1] = *(const uint4*)(Bh + o1);
        p[3][0] = *(const uint4*)(Bl + o0); p[3][1] = *(const uint4*)(Bl + o1);
    }

    float acc[4][4][4];
    #pragma unroll
    for (int mi = 0; mi < 4; ++mi)
        #pragma unroll
        for (int ni = 0; ni < 4; ++ni)
            #pragma unroll
            for (int e = 0; e < 4; ++e)
                acc[mi][ni][e] = 0.f;

    const int m0 = (wid & 1) * 64;
    const int n0 = (wid >> 1) * 32;

    uint32_t baseA_h = smem_u32(&sm[0][0]);
    uint32_t baseA_l = smem_u32(&sm[1][0]);
    uint32_t baseB_h = smem_u32(&sm[2][0]);
    uint32_t baseB_l = smem_u32(&sm[3][0]);

    const int d0 = r0c * LDT + k80;
    const int d1 = r1c * LDT + k81;

    const int nkc = K >> 5;
    for (int kc = 0; kc < nkc; ++kc) {
        #pragma unroll
        for (int t = 0; t < 4; ++t) {
            *(uint4*)&sm[t][d0] = p[t][0];
            *(uint4*)&sm[t][d1] = p[t][1];
        }
        __syncthreads();

        if (kc + 1 < nkc) {
            const long long o0 = (long long)r0c * K + (kc + 1) * 32 + k80;
            const long long o1 = (long long)r1c * K + (kc + 1) * 32 + k81;
            p[0][0] = *(const uint4*)(Ah + o0); p[0][1] = *(const uint4*)(Ah + o1);
            p[1][0] = *(const uint4*)(Al + o0); p[1][1] = *(const uint4*)(Al + o1);
            p[2][0] = *(const uint4*)(Bh + o0); p[2][1] = *(const uint4*)(Bh + o1);
            p[3][0] = *(const uint4*)(Bl + o0); p[3][1] = *(const uint4*)(Bl + o1);
        }

        #pragma unroll
        for (int s = 0; s < 2; ++s) {
            const uint32_t aoff = (uint32_t)((m0 + (lane & 15)) * (LDT * 2)
                                 + s * 32 + ((lane >> 4) << 4));
            const uint32_t boff = (uint32_t)((n0 + (lane & 7)) * (LDT * 2)
                                 + s * 32 + (((lane >> 3) & 1) << 4));
            uint32_t ah[4][4], al[4][4], bh[4][2], bl[4][2];
            #pragma unroll
            for (int mi = 0; mi < 4; ++mi) {
                ldsm4(baseA_h + aoff + mi * 16 * (LDT * 2), ah[mi]);
                ldsm4(baseA_l + aoff + mi * 16 * (LDT * 2), al[mi]);
            }
            #pragma unroll
            for (int ni = 0; ni < 4; ++ni) {
                ldsm2(baseB_h + boff + ni * 8 * (LDT * 2), bh[ni]);
                ldsm2(baseB_l + boff + ni * 8 * (LDT * 2), bl[ni]);
            }
            #pragma unroll
            for (int mi = 0; mi < 4; ++mi)
                #pragma unroll
                for (int ni = 0; ni < 4; ++ni) {
                    mma_bf16(acc[mi][ni], ah[mi], bh[ni]);
                    mma_bf16(acc[mi][ni], al[mi], bh[ni]);
                    mma_bf16(acc[mi][ni], ah[mi], bl[ni]);
                }
        }
        __syncthreads();
    }

    // epilogue: thread holds rows (m0+mi*16 + lane/4, +8), cols (n0+ni*8 + (lane%4)*2, +1)
    #pragma unroll
    for (int mi = 0; mi < 4; ++mi) {
        const int r = m0 + mi * 16 + (lane >> 2);
        const float bv0 = BIAS ? bias[mt * 128 + r] : 0.f;
        const float bv1 = BIAS ? bias[mt * 128 + r + 8] : 0.f;
        #pragma unroll
        for (int ni = 0; ni < 4; ++ni) {
            const int cc = n0 + ni * 8 + ((lane & 3) << 1);
            float2 v0 = make_float2(acc[mi][ni][0] + bv0, acc[mi][ni][1] + bv0);
            float2 v1 = make_float2(acc[mi][ni][2] + bv1, acc[mi][ni][3] + bv1);
            *(float2*)(Cb + (long long)r * NTOK + cc)       = v0;
            *(float2*)(Cb + (long long)(r + 8) * NTOK + cc) = v1;
        }
    }
}

// =====================================================================
// x [b][c][n] fp32 -> x^T hi/lo bf16 [b][n][c]   (32x32 smem transpose)
// =====================================================================
__global__ void convx_kernel(const float* __restrict__ x)
{
    __shared__ float t[32][33];
    const int n0 = blockIdx.x * 32, c0 = blockIdx.y * 32, b = blockIdx.z;
    const int tx = threadIdx.x, ty = threadIdx.y;
    const float* xb = x + ((long long)b * CIN + c0) * NTOK + n0;
    #pragma unroll
    for (int i = 0; i < 4; ++i)
        t[ty + i * 8][tx] = xb[(long long)(ty + i * 8) * NTOK + tx];
    __syncthreads();
    #pragma unroll
    for (int i = 0; i < 4; ++i) {
        const int n = ty + i * 8;
        const float v = t[tx][n];
        const __nv_bfloat16 hi = __float2bfloat16(v);
        const __nv_bfloat16 lo = __float2bfloat16(v - __bfloat162float(hi));
        const long long o = ((long long)b * NTOK + n0 + n) * CIN + c0 + tx;
        g_xt_hi[o] = hi;
        g_xt_lo[o] = lo;
    }
}

// W_qkv [768][128] fp32 -> hi/lo bf16 same layout
__global__ void convw_kernel(const float* __restrict__ w)
{
    const int i = blockIdx.x * 256 + threadIdx.x;
    const float v = w[i];
    const __nv_bfloat16 hi = __float2bfloat16(v);
    g_wq_hi[i] = hi;
    g_wq_lo[i] = __float2bfloat16(v - __bfloat162float(hi));
}

// =====================================================================
// q softmax over 32 feature dims per head, * SCALE; writes transposed
// bf16 hi/lo [b][n][h*32+d] for GEMM2's B operand.
// =====================================================================
__global__ void qsoftmax_kernel()
{
    const int idx = blockIdx.x * blockDim.x + threadIdx.x;  // 4*8*32768
    const int n  = idx & (NTOK - 1);
    const int hb = idx >> 15;
    const int h  = hb & (NHEAD - 1);
    const int b  = hb >> 3;

    const float* qp = g_qkv + ((long long)b * OQKV + (long long)h * DHEAD) * NTOK + n;

    float v[32];
    float m = -1e30f;
    #pragma unroll
    for (int d = 0; d < 32; ++d) {
        v[d] = qp[(long long)d * NTOK];
        m = fmaxf(m, v[d]);
    }
    float s = 0.f;
    #pragma unroll
    for (int d = 0; d < 32; ++d) {
        v[d] = __expf(v[d] - m);
        s += v[d];
    }
    const float inv = SCALE / s;

    __align__(16) __nv_bfloat16 hb16[32], lb16[32];
    #pragma unroll
    for (int d = 0; d < 32; ++d) {
        const float q = v[d] * inv;
        const __nv_bfloat16 hi = __float2bfloat16(q);
        hb16[d] = hi;
        lb16[d] = __float2bfloat16(q - __bfloat162float(hi));
    }
    const long long o = ((long long)b * NTOK + n) * HID + h * DHEAD;
    #pragma unroll
    for (int j = 0; j < 4; ++j) {
        *(uint4*)(&g_qt_hi[o + j * 8]) = ((const uint4*)hb16)[j];
        *(uint4*)(&g_qt_lo[o + j * 8]) = ((const uint4*)lb16)[j];
    }
}

// =====================================================================
// context: ctx[b,h,d,e] += sum_n exp(k[d,n]) * v[e,n];  ksum += sum exp(k)
// (no max subtraction: k ~ N(0,1); the exp(-max) cancels in mcombine)
// =====================================================================
__global__ __launch_bounds__(256, 2)
void context_kernel()
{
    const int b = blockIdx.z, h = blockIdx.y, cx = blockIdx.x;
    const int t = threadIdx.x;
    const float* kbase = g_qkv + ((long long)b * OQKV + HID     + h * DHEAD) * NTOK;
    const float* vbase = g_qkv + ((long long)b * OQKV + 2 * HID + h * DHEAD) * NTOK;

    __shared__ float ks[32][33];
    __shared__ float vs[32][33];
    __shared__ float red[32][33];

    for (int i = t; i < 1024; i += 256) red[i >> 5][i & 31] = 0.f;

    const int ld = t >> 3;
    const int ln = (t & 7) << 2;
    const int slot = t >> 4;
    const int l    = t & 15;
    const int ti   = l >> 2;
    const int tj   = l & 3;

    float acc[8][8];
    #pragma unroll
    for (int i = 0; i < 8; ++i)
        #pragma unroll
        for (int j = 0; j < 8; ++j)
            acc[i][j] = 0.f;
    float ksum_part = 0.f;

    const int nbase0 = cx * (NTOK / 16);
    const int NS = (NTOK / 16) / 32;

    const float* krow = kbase + (long long)ld * NTOK + nbase0 + ln;
    const float* vrow = vbase + (long long)ld * NTOK + nbase0 + ln;
    float4 kr = *(const float4*)krow;
    float4 vr = *(const float4*)vrow;

    for (int slab = 0; slab < NS; ++slab) {
        const float e0 = __expf(kr.x), e1 = __expf(kr.y);
        const float e2 = __expf(kr.z), e3 = __expf(kr.w);
        ksum_part += (e0 + e1) + (e2 + e3);
        ks[ld][ln] = e0; ks[ld][ln + 1] = e1; ks[ld][ln + 2] = e2; ks[ld][ln + 3] = e3;
        vs[ld][ln] = vr.x; vs[ld][ln + 1] = vr.y; vs[ld][ln + 2] = vr.z; vs[ld][ln + 3] = vr.w;
        __syncthreads();

        if (slab + 1 < NS) {
            kr = *(const float4*)(krow + (slab + 1) * 32);
            vr = *(const float4*)(vrow + (slab + 1) * 32);
        }

        #pragma unroll
        for (int q = 0; q < 2; ++q) {
            const int n = slot * 2 + q;
            float ka[8], va[8];
            #pragma unroll
            for (int i = 0; i < 8; ++i) ka[i] = ks[ti * 8 + i][n];
            #pragma unroll
            for (int j = 0; j < 8; ++j) va[j] = vs[tj * 8 + j][n];
            #pragma unroll
            for (int i = 0; i < 8; ++i)
                #pragma unroll
                for (int j = 0; j < 8; ++j)
                    acc[i][j] = fmaf(ka[i], va[j], acc[i][j]);
        }
        __syncthreads();
    }

    #pragma unroll
    for (int o = 4; o > 0; o >>= 1)
        ksum_part += __shfl_down_sync(0xffffffffu, ksum_part, o, 8);
    if ((t & 7) == 0)
        atomicAdd(&g_ksum[(b * NHEAD + h) * DHEAD + ld], ksum_part);

    #pragma unroll
    for (int i = 0; i < 8; ++i)
        #pragma unroll
        for (int j = 0; j < 8; ++j)
            atomicAdd(&red[ti * 8 + i][tj * 8 + j], acc[i][j]);
    __syncthreads();

    float* ctx = g_ctx + (b * NHEAD + h) * (DHEAD * DHEAD);
    for (int i = t; i < 1024; i += 256)
        atomicAdd(&ctx[i], red[i >> 5][i & 31]);
}

// =====================================================================
// M[b][co][h*32+d] = (sum_e W_out[co][h*32+e] * ctx[b,h,d,e]) / ksum[b,h,d]
// emitted as bf16 hi/lo for GEMM2's A operand.
// =====================================================================
__global__ void mcombine_kernel(const float* __restrict__ w_out)
{
    const int idx = blockIdx.x * 256 + threadIdx.x;   // 4*128*256
    const int col = idx & 255;
    const int co  = (idx >> 8) & 127;
    const int b   = idx >> 15;
    const int h = col >> 5, d = col & 31;

    const float* wrow = w_out + co * HID + h * DHEAD;
    const float* cr = g_ctx + ((b * NHEAD + h) * DHEAD + d) * DHEAD;
    float s = 0.f;
    #pragma unroll
    for (int e = 0; e < 32; ++e) s = fmaf(wrow[e], cr[e], s);
    const float m = s / g_ksum[b * HID + col];

    const long long o = ((long long)b * CIN + co) * HID + col;
    const __nv_bfloat16 hi = __float2bfloat16(m);
    g_M_hi[o] = hi;
    g_M_lo[o] = __float2bfloat16(m - __bfloat162float(hi));
}

// =====================================================================
extern "C" void kernel_launch(void* const* d_in, const int* in_sizes, int n_in,
                              void* d_out, int out_size)
{
    const float* x     = (const float*)d_in[0];   // [4,128,32768]
    const float* w_qkv = (const float*)d_in[1];   // [768,128]
    const float* w_out = (const float*)d_in[2];   // [128,256]
    const float* b_out = (const float*)d_in[3];   // [128]
    float* out = (float*)d_out;                   // [4,128,32768]

    float *qkv_p = nullptr, *ctx_p = nullptr, *ksum_p = nullptr;
    __nv_bfloat16 *xth, *xtl, *wqh, *wql, *qth, *qtl, *mh, *ml;
    cudaGetSymbolAddress((void**)&qkv_p, g_qkv);
    cudaGetSymbolAddress((void**)&ctx_p, g_ctx);
    cudaGetSymbolAddress((void**)&ksum_p, g_ksum);
    cudaGetSymbolAddress((void**)&xth, g_xt_hi);
    cudaGetSymbolAddress((void**)&xtl, g_xt_lo);
    cudaGetSymbolAddress((void**)&wqh, g_wq_hi);
    cudaGetSymbolAddress((void**)&wql, g_wq_lo);
    cudaGetSymbolAddress((void**)&qth, g_qt_hi);
    cudaGetSymbolAddress((void**)&qtl, g_qt_lo);
    cudaGetSymbolAddress((void**)&mh, g_M_hi);
    cudaGetSymbolAddress((void**)&ml, g_M_lo);

    // 0) convert inputs to bf16 hi/lo (x transposed)
    convx_kernel<<<dim3(NTOK / 32, CIN / 32, NB), dim3(32, 8)>>>(x);
    convw_kernel<<<(OQKV * CIN) / 256, 256>>>(w_qkv);

    // 1) qkv = W_qkv @ x  (HMMA, 3-term bf16 split), fp32 out -> g_qkv
    gemm_mma_kernel<false><<<dim3(NTOK / 128, OQKV / 128, NB), 256>>>(
        wqh, wql, xth, xtl, qkv_p, nullptr, CIN,
        0LL, (long long)NTOK * CIN, (long long)OQKV * NTOK);

    // 2) q softmax -> transposed bf16 hi/lo
    qsoftmax_kernel<<<(NB * NHEAD * NTOK) / 256, 256>>>();

    // 3) zero accumulators
    cudaMemsetAsync(ctx_p, 0, sizeof(float) * NB * NHEAD * DHEAD * DHEAD);
    cudaMemsetAsync(ksum_p, 0, sizeof(float) * NB * HID);

    // 4) context + ksum
    context_kernel<<<dim3(16, NHEAD, NB), 256>>>();

    // 5) fold projection matrix -> bf16 hi/lo
    mcombine_kernel<<<(NB * CIN * HID) / 256, 256>>>(w_out);

    // 6) out = M @ q_soft + b_out  (HMMA, K=256)
    gemm_mma_kernel<true><<<dim3(NTOK / 128, 1, NB), 256>>>(
        mh, ml, qth, qtl, out, b_out, HID,
        (long long)CIN * HID, (long long)NTOK * HID, (long long)CIN * NTOK);
}